// round 1
// baseline (speedup 1.0000x reference)
#include <cuda_runtime.h>

#define T_TOK 2048
#define SDIM  1024
#define EDIM  1024
#define HID   150
#define MAXW  10
#define TM    8     // tokens per MLP block

__device__ float g_attns[T_TOK];

// ---------------------------------------------------------------------------
// Kernel 1: fused 3-layer MLP -> per-token scalar score
// One block = 8 tokens. States tile staged in SMEM as float4.
// Each warp computes 4 hidden units x 8 tokens per pass (register reuse of
// SMEM reads), warp-butterfly reduction over K.
// ---------------------------------------------------------------------------
__global__ __launch_bounds__(256) void mlp_kernel(
    const float* __restrict__ states,
    const float* __restrict__ w1, const float* __restrict__ b1,
    const float* __restrict__ w2, const float* __restrict__ b2,
    const float* __restrict__ w3, const float* __restrict__ b3)
{
    __shared__ float4 As4[TM][SDIM / 4];      // 32 KB
    __shared__ float  h1s[TM][HID + 2];
    __shared__ float  h2s[TM][HID + 2];

    const int tid  = threadIdx.x;
    const int lane = tid & 31;
    const int w    = tid >> 5;
    const int t0   = blockIdx.x * TM;

    // stage 8 token states into SMEM (coalesced float4)
    const float4* st4 = (const float4*)states;
    for (int idx = tid; idx < TM * (SDIM / 4); idx += 256) {
        int t = idx >> 8, k = idx & 255;
        As4[t][k] = st4[(size_t)(t0 + t) * (SDIM / 4) + k];
    }
    __syncthreads();

    // ---------------- layer 1: h1 = relu(states @ w1^T + b1) ----------------
    for (int g = w; g < 38; g += 8) {          // 38*4 = 152 >= 150 hidden units
        const int j0 = g * 4;
        const float4* wr0 = (const float4*)(w1 + (size_t)min(j0 + 0, HID - 1) * SDIM);
        const float4* wr1 = (const float4*)(w1 + (size_t)min(j0 + 1, HID - 1) * SDIM);
        const float4* wr2 = (const float4*)(w1 + (size_t)min(j0 + 2, HID - 1) * SDIM);
        const float4* wr3 = (const float4*)(w1 + (size_t)min(j0 + 3, HID - 1) * SDIM);

        float acc[4][TM];
        #pragma unroll
        for (int u = 0; u < 4; u++)
            #pragma unroll
            for (int t = 0; t < TM; t++) acc[u][t] = 0.f;

        for (int c = lane; c < SDIM / 4; c += 32) {
            float4 wv0 = wr0[c], wv1 = wr1[c], wv2 = wr2[c], wv3 = wr3[c];
            #pragma unroll
            for (int t = 0; t < TM; t++) {
                float4 av = As4[t][c];
                acc[0][t] += wv0.x * av.x + wv0.y * av.y + wv0.z * av.z + wv0.w * av.w;
                acc[1][t] += wv1.x * av.x + wv1.y * av.y + wv1.z * av.z + wv1.w * av.w;
                acc[2][t] += wv2.x * av.x + wv2.y * av.y + wv2.z * av.z + wv2.w * av.w;
                acc[3][t] += wv3.x * av.x + wv3.y * av.y + wv3.z * av.z + wv3.w * av.w;
            }
        }
        // butterfly-reduce all 32 accumulators across the warp
        #pragma unroll
        for (int off = 16; off; off >>= 1)
            #pragma unroll
            for (int u = 0; u < 4; u++)
                #pragma unroll
                for (int t = 0; t < TM; t++)
                    acc[u][t] += __shfl_xor_sync(0xffffffffu, acc[u][t], off);

        // lane l stores value (u = l>>3, t = l&7) — select without dyn index
        float v = 0.f;
        #pragma unroll
        for (int u = 0; u < 4; u++)
            #pragma unroll
            for (int t = 0; t < TM; t++)
                if (lane == u * 8 + t) v = acc[u][t];
        int ju = j0 + (lane >> 3);
        int tu = lane & 7;
        if (ju < HID) h1s[tu][ju] = fmaxf(v + b1[ju], 0.f);
    }
    __syncthreads();

    // ---------------- layer 2: h2 = relu(h1 @ w2^T + b2) --------------------
    for (int g = w; g < 38; g += 8) {
        const int j0 = g * 4;
        const float* r0 = w2 + (size_t)min(j0 + 0, HID - 1) * HID;
        const float* r1 = w2 + (size_t)min(j0 + 1, HID - 1) * HID;
        const float* r2 = w2 + (size_t)min(j0 + 2, HID - 1) * HID;
        const float* r3 = w2 + (size_t)min(j0 + 3, HID - 1) * HID;

        float acc[4][TM];
        #pragma unroll
        for (int u = 0; u < 4; u++)
            #pragma unroll
            for (int t = 0; t < TM; t++) acc[u][t] = 0.f;

        for (int kk = lane; kk < HID; kk += 32) {
            float wv0 = r0[kk], wv1 = r1[kk], wv2 = r2[kk], wv3 = r3[kk];
            #pragma unroll
            for (int t = 0; t < TM; t++) {
                float hv = h1s[t][kk];
                acc[0][t] += wv0 * hv;
                acc[1][t] += wv1 * hv;
                acc[2][t] += wv2 * hv;
                acc[3][t] += wv3 * hv;
            }
        }
        #pragma unroll
        for (int off = 16; off; off >>= 1)
            #pragma unroll
            for (int u = 0; u < 4; u++)
                #pragma unroll
                for (int t = 0; t < TM; t++)
                    acc[u][t] += __shfl_xor_sync(0xffffffffu, acc[u][t], off);

        float v = 0.f;
        #pragma unroll
        for (int u = 0; u < 4; u++)
            #pragma unroll
            for (int t = 0; t < TM; t++)
                if (lane == u * 8 + t) v = acc[u][t];
        int ju = j0 + (lane >> 3);
        int tu = lane & 7;
        if (ju < HID) h2s[tu][ju] = fmaxf(v + b2[ju], 0.f);
    }
    __syncthreads();

    // ---------------- layer 3: attns = h2 @ w3^T + b3 -----------------------
    if (w == 0) {
        float acc[TM];
        #pragma unroll
        for (int t = 0; t < TM; t++) acc[t] = 0.f;
        for (int kk = lane; kk < HID; kk += 32) {
            float wv = w3[kk];
            #pragma unroll
            for (int t = 0; t < TM; t++) acc[t] += wv * h2s[t][kk];
        }
        #pragma unroll
        for (int off = 16; off; off >>= 1)
            #pragma unroll
            for (int t = 0; t < TM; t++)
                acc[t] += __shfl_xor_sync(0xffffffffu, acc[t], off);
        float v = 0.f;
        #pragma unroll
        for (int t = 0; t < TM; t++)
            if (lane == t) v = acc[t];
        if (lane < TM) g_attns[t0 + lane] = v + b3[0];
    }
}

// ---------------------------------------------------------------------------
// Kernel 2: span assembly. One block per span start r; all widths n=1..10
// computed with a running softmax numerator/denominator, sharing embed reads.
// Thread tid owns float4 element-group tid (1024 floats = 256 float4 = 256 thr)
// ---------------------------------------------------------------------------
__global__ __launch_bounds__(256) void assemble_kernel(
    const float* __restrict__ embeds,
    const float* __restrict__ states,
    float* __restrict__ out)
{
    const int r   = blockIdx.x;
    const int tid = threadIdx.x;
    const int nmax = min(MAXW, T_TOK - r);

    __shared__ float ws[MAXW];
    __shared__ float invden[MAXW];

    if (tid == 0) {
        float a[MAXW];
        float m = -1e30f;
        for (int i = 0; i < nmax; i++) {
            a[i] = g_attns[r + i];
            m = fmaxf(m, a[i]);
        }
        float den = 0.f;
        for (int i = 0; i < nmax; i++) {
            float e = __expf(a[i] - m);
            ws[i] = e;
            den += e;
            invden[i] = 1.0f / den;
        }
    }
    __syncthreads();

    const float4* st4 = (const float4*)states;
    const float4* em4 = (const float4*)embeds;
    float4* out4 = (float4*)out;

    const float4 s0 = st4[r * 256 + tid];
    float4 num = make_float4(0.f, 0.f, 0.f, 0.f);

    for (int i = 0; i < nmax; i++) {
        const float wv = ws[i];
        const float4 e = em4[(r + i) * 256 + tid];
        num.x += wv * e.x; num.y += wv * e.y;
        num.z += wv * e.z; num.w += wv * e.w;

        const int n = i + 1;
        // section offset: sum_{m=1}^{n-1} (2049 - m) = (n-1)*2049 - n(n-1)/2
        const int row  = (n - 1) * (T_TOK + 1) - (n * (n - 1)) / 2 + r;
        const int base = row * 768;                // 3072 floats / 4

        out4[base + tid]       = s0;                        // start state
        out4[base + 256 + tid] = st4[(r + n - 1) * 256 + tid]; // end state
        const float id = invden[i];
        out4[base + 512 + tid] = make_float4(num.x * id, num.y * id,
                                             num.z * id, num.w * id);
    }
}

// ---------------------------------------------------------------------------
extern "C" void kernel_launch(void* const* d_in, const int* in_sizes, int n_in,
                              void* d_out, int out_size) {
    const float* embeds = (const float*)d_in[0];
    const float* states = (const float*)d_in[1];
    const float* w1     = (const float*)d_in[2];
    const float* b1     = (const float*)d_in[3];
    const float* w2     = (const float*)d_in[4];
    const float* b2     = (const float*)d_in[5];
    const float* w3     = (const float*)d_in[6];
    const float* b3     = (const float*)d_in[7];
    float* out = (float*)d_out;

    mlp_kernel<<<T_TOK / TM, 256>>>(states, w1, b1, w2, b2, w3, b3);
    assemble_kernel<<<T_TOK, 256>>>(embeds, states, out);
}